// round 15
// baseline (speedup 1.0000x reference)
#include <cuda_runtime.h>
#include <cuda_bf16.h>

// ValScores: per-class mean of preds rows (segment reduction by label) + EMA.
//   out[c,:] = cnt[c]>0 ? 0.1*mean_c(preds) + 0.9*val_preds[c,:] : val_preds[c,:]
//
// FINAL — byte-identical to Round 13, the session optimum (92.9us):
//   k_scatter_v4 : KSUB=8 bucket scatter, int4 label loads (4 independent
//                  atomics/thread). Measured scatter+boundary gap: 2.4us —
//                  best of int4(KSUB=8/16) and scalar(1 elem/thread) variants.
//   k_reduce_v4  : one CTA per class, 256 threads, __launch_bounds__(256,8)
//                  pins 32 regs -> 8 CTAs/SM -> grid=1000 is ONE wave.
//                  Whole contiguous 4000B rows, 4x float4 __ldcs unroll
//                  (the 32-reg MLP maximum). Measured 89.95-90.5us @ DRAM
//                  ~75% — the pattern ceiling for random-4KB gathers.
//
// Experiment matrix (15 rounds): ticket stealing 116; column split 119; row
// split +spin 99 / +REDG 97; fused grid barrier 101; 8-row unroll 119 (reg
// starved); shfl scan 105 (regs 32->40, two waves); KSUB=16 96.4-96.8;
// scalar scatter 95.0. All inferior. Invariants: whole rows per CTA, 32
// regs, single wave, zero cross-CTA coordination in the reduce.

#define C_MAX   1024
#define KSUB    8
#define CAP     256            // per sub-list capacity (expected ~16 +- 4)
#define SMAX    (KSUB * CAP)   // 2048 indices, 8KB smem
#define GAMMA   0.9f
#define ONE_MINUS_GAMMA 0.1f

__device__ int g_cursor[C_MAX * KSUB];        // zero-init at module load
__device__ int g_rowidx[C_MAX * KSUB * CAP];  // 8 MB scratch

// ---------------------------------------------------------------------------
// Scatter: each thread handles 4 consecutive elements via one int4 label load.
// Sub-cursor chosen from the element index low bits -> adjacent elements of
// the same class hit different L2 lines.
// ---------------------------------------------------------------------------
__global__ __launch_bounds__(256) void k_scatter_v4(const int4* __restrict__ labels4, int n4) {
    int t = blockIdx.x * blockDim.x + threadIdx.x;
    if (t >= n4) return;
    int4 L = labels4[t];
    int i0 = t * 4;

    int s0 = (i0 + 0) & (KSUB - 1);
    int s1 = (i0 + 1) & (KSUB - 1);
    int s2 = (i0 + 2) & (KSUB - 1);
    int s3 = (i0 + 3) & (KSUB - 1);

    int b0 = L.x * KSUB + s0;
    int b1 = L.y * KSUB + s1;
    int b2 = L.z * KSUB + s2;
    int b3 = L.w * KSUB + s3;

    int p0 = atomicAdd(&g_cursor[b0], 1);
    int p1 = atomicAdd(&g_cursor[b1], 1);
    int p2 = atomicAdd(&g_cursor[b2], 1);
    int p3 = atomicAdd(&g_cursor[b3], 1);

    if (p0 < CAP) g_rowidx[b0 * CAP + p0] = i0 + 0;
    if (p1 < CAP) g_rowidx[b1 * CAP + p1] = i0 + 1;
    if (p2 < CAP) g_rowidx[b2 * CAP + p2] = i0 + 2;
    if (p3 < CAP) g_rowidx[b3 * CAP + p3] = i0 + 3;
}

// Scalar fallback for N % 4 != 0.
__global__ __launch_bounds__(256) void k_scatter_s(const int* __restrict__ labels, int N) {
    int i = blockIdx.x * blockDim.x + threadIdx.x;
    if (i >= N) return;
    int b = labels[i] * KSUB + (i & (KSUB - 1));
    int p = atomicAdd(&g_cursor[b], 1);
    if (p < CAP) g_rowidx[b * CAP + p] = i;
}

// ---------------------------------------------------------------------------
// Reduce: one CTA per class, 256 threads, pinned to 8 CTAs/SM (<=32 regs).
// Thread t owns cols [4t, 4t+3].
// ---------------------------------------------------------------------------
__global__ __launch_bounds__(256, 8) void k_reduce_v4(
    const float* __restrict__ preds,
    const float* __restrict__ val_preds,
    float* __restrict__ out,
    int C)
{
    int c   = blockIdx.x;
    int tid = threadIdx.x;

    __shared__ int s_base[KSUB + 1];
    __shared__ int s_idx[SMAX];

    // Per-sub counts -> prefix (KSUB=8, done by thread 0; trivial).
    if (tid == 0) {
        int tot = 0;
        #pragma unroll
        for (int s = 0; s < KSUB; ++s) {
            s_base[s] = tot;
            int cs = g_cursor[c * KSUB + s];
            tot += (cs < CAP ? cs : CAP);
        }
        s_base[KSUB] = tot;
    }
    __syncthreads();

    // Cooperative stage of all row indices into smem (compacted).
    #pragma unroll
    for (int s = 0; s < KSUB; ++s) {
        int lo = s_base[s], cs = s_base[s + 1] - lo;
        const int* src = &g_rowidx[(c * KSUB + s) * CAP];
        for (int j = tid; j < cs; j += 256) s_idx[lo + j] = src[j];
    }
    __syncthreads();

    // Sole reader of this class's cursors -> reset for next graph replay.
    if (tid < KSUB) g_cursor[c * KSUB + tid] = 0;

    int cnt  = s_base[KSUB];
    int col4 = tid * 4;
    if (col4 >= C) return;

    float ax = 0.f, ay = 0.f, az = 0.f, aw = 0.f;
    int r = 0;
    // 4 independent 16B streaming loads in flight per thread
    // (the 32-register MLP maximum that preserves 8 CTAs/SM).
    for (; r + 3 < cnt; r += 4) {
        const float4* p0 = (const float4*)(preds + (size_t)s_idx[r + 0] * C + col4);
        const float4* p1 = (const float4*)(preds + (size_t)s_idx[r + 1] * C + col4);
        const float4* p2 = (const float4*)(preds + (size_t)s_idx[r + 2] * C + col4);
        const float4* p3 = (const float4*)(preds + (size_t)s_idx[r + 3] * C + col4);
        float4 v0 = __ldcs(p0);
        float4 v1 = __ldcs(p1);
        float4 v2 = __ldcs(p2);
        float4 v3 = __ldcs(p3);
        ax += v0.x; ay += v0.y; az += v0.z; aw += v0.w;
        ax += v1.x; ay += v1.y; az += v1.z; aw += v1.w;
        ax += v2.x; ay += v2.y; az += v2.z; aw += v2.w;
        ax += v3.x; ay += v3.y; az += v3.z; aw += v3.w;
    }
    for (; r < cnt; ++r) {
        float4 v = __ldcs((const float4*)(preds + (size_t)s_idx[r] * C + col4));
        ax += v.x; ay += v.y; az += v.z; aw += v.w;
    }

    float4 vp = *(const float4*)(val_preds + (size_t)c * C + col4);
    float4 o;
    if (cnt > 0) {
        float inv = ONE_MINUS_GAMMA / (float)cnt;
        o.x = ax * inv + GAMMA * vp.x;
        o.y = ay * inv + GAMMA * vp.y;
        o.z = az * inv + GAMMA * vp.z;
        o.w = aw * inv + GAMMA * vp.w;
    } else {
        o = vp;
    }
    *(float4*)(out + (size_t)c * C + col4) = o;
}

// Scalar-column fallback (C % 4 != 0 or C > 1024): 1 CTA per class.
__global__ __launch_bounds__(256) void k_reduce_s(
    const float* __restrict__ preds,
    const float* __restrict__ val_preds,
    float* __restrict__ out,
    int C)
{
    int c   = blockIdx.x;
    int tid = threadIdx.x;

    __shared__ int s_base[KSUB + 1];
    __shared__ int s_idx[SMAX];

    if (tid == 0) {
        int tot = 0;
        #pragma unroll
        for (int s = 0; s < KSUB; ++s) {
            s_base[s] = tot;
            int cs = g_cursor[c * KSUB + s];
            tot += (cs < CAP ? cs : CAP);
        }
        s_base[KSUB] = tot;
    }
    __syncthreads();
    #pragma unroll
    for (int s = 0; s < KSUB; ++s) {
        int lo = s_base[s], cs = s_base[s + 1] - lo;
        const int* src = &g_rowidx[(c * KSUB + s) * CAP];
        for (int j = tid; j < cs; j += 256) s_idx[lo + j] = src[j];
    }
    __syncthreads();
    if (tid < KSUB) g_cursor[c * KSUB + tid] = 0;

    int cnt = s_base[KSUB];
    for (int col = tid; col < C; col += 256) {
        float acc = 0.f;
        for (int r = 0; r < cnt; ++r)
            acc += __ldcs(preds + (size_t)s_idx[r] * C + col);
        float vp = val_preds[(size_t)c * C + col];
        out[(size_t)c * C + col] =
            (cnt > 0) ? (ONE_MINUS_GAMMA * acc / (float)cnt + GAMMA * vp) : vp;
    }
}

extern "C" void kernel_launch(void* const* d_in, const int* in_sizes, int n_in,
                              void* d_out, int out_size) {
    const float* preds     = (const float*)d_in[0];
    const int*   labels    = (const int*)  d_in[1];
    const float* val_preds = (const float*)d_in[2];
    float*       out       = (float*)d_out;

    const int N = in_sizes[1];       // 131072
    const int C = in_sizes[0] / N;   // 1000

    if ((N & 3) == 0) {
        int n4 = N / 4;
        k_scatter_v4<<<(n4 + 255) / 256, 256>>>((const int4*)labels, n4);
    } else {
        k_scatter_s<<<(N + 255) / 256, 256>>>(labels, N);
    }

    if ((C % 4) == 0 && C <= C_MAX) {
        k_reduce_v4<<<C, 256>>>(preds, val_preds, out, C);
    } else {
        k_reduce_s<<<C, 256>>>(preds, val_preds, out, C);
    }
}

// round 16
// speedup vs baseline: 1.0040x; 1.0040x over previous
#include <cuda_runtime.h>
#include <cuda_bf16.h>

// ValScores: per-class mean of preds rows (segment reduction by label) + EMA.
//   out[c,:] = cnt[c]>0 ? 0.1*mean_c(preds) + 0.9*val_preds[c,:] : val_preds[c,:]
//
// CONVERGED FINAL (byte-identical to Round 13, session best 92.9us; identical
// binary measured 92.9-95.4us across runs -> +-2.5us machine variance):
//   k_scatter_v4 : KSUB=8 bucket scatter, int4 label loads (4 independent
//                  atomics/thread). Best measured scatter+boundary: 2.4us.
//   k_reduce_v4  : one CTA per class, 256 threads, __launch_bounds__(256,8)
//                  pins 32 regs -> 8 CTAs/SM -> grid=1000 is ONE wave.
//                  Whole contiguous 4000B rows, 4x float4 __ldcs unroll
//                  (the 32-reg MLP maximum). 89.95-91.5us @ DRAM 73-75% —
//                  the random-4KB-gather ceiling (class rows average ~4MB
//                  apart; no ordering can create DRAM row locality).
//
// Experiment matrix (15 rounds), all inferior:
//   ticket stealing 116 | column split 119 | row split +spin 99 / +REDG 97
//   fused grid barrier 101 | 8-row unroll 119 (reg-starved) | shfl scan 105
//   (regs 32->40, two waves) | KSUB=16 96.4-96.8 | scalar scatter 95.0
// Invariants: whole rows per CTA; 32 regs; single wave; zero cross-CTA
// coordination in the reduce; all device state returns to zero each replay.

#define C_MAX   1024
#define KSUB    8
#define CAP     256            // per sub-list capacity (expected ~16 +- 4)
#define SMAX    (KSUB * CAP)   // 2048 indices, 8KB smem
#define GAMMA   0.9f
#define ONE_MINUS_GAMMA 0.1f

__device__ int g_cursor[C_MAX * KSUB];        // zero-init at module load
__device__ int g_rowidx[C_MAX * KSUB * CAP];  // 8 MB scratch

// ---------------------------------------------------------------------------
// Scatter: each thread handles 4 consecutive elements via one int4 label load.
// Sub-cursor chosen from the element index low bits -> adjacent elements of
// the same class hit different L2 lines.
// ---------------------------------------------------------------------------
__global__ __launch_bounds__(256) void k_scatter_v4(const int4* __restrict__ labels4, int n4) {
    int t = blockIdx.x * blockDim.x + threadIdx.x;
    if (t >= n4) return;
    int4 L = labels4[t];
    int i0 = t * 4;

    int s0 = (i0 + 0) & (KSUB - 1);
    int s1 = (i0 + 1) & (KSUB - 1);
    int s2 = (i0 + 2) & (KSUB - 1);
    int s3 = (i0 + 3) & (KSUB - 1);

    int b0 = L.x * KSUB + s0;
    int b1 = L.y * KSUB + s1;
    int b2 = L.z * KSUB + s2;
    int b3 = L.w * KSUB + s3;

    int p0 = atomicAdd(&g_cursor[b0], 1);
    int p1 = atomicAdd(&g_cursor[b1], 1);
    int p2 = atomicAdd(&g_cursor[b2], 1);
    int p3 = atomicAdd(&g_cursor[b3], 1);

    if (p0 < CAP) g_rowidx[b0 * CAP + p0] = i0 + 0;
    if (p1 < CAP) g_rowidx[b1 * CAP + p1] = i0 + 1;
    if (p2 < CAP) g_rowidx[b2 * CAP + p2] = i0 + 2;
    if (p3 < CAP) g_rowidx[b3 * CAP + p3] = i0 + 3;
}

// Scalar fallback for N % 4 != 0.
__global__ __launch_bounds__(256) void k_scatter_s(const int* __restrict__ labels, int N) {
    int i = blockIdx.x * blockDim.x + threadIdx.x;
    if (i >= N) return;
    int b = labels[i] * KSUB + (i & (KSUB - 1));
    int p = atomicAdd(&g_cursor[b], 1);
    if (p < CAP) g_rowidx[b * CAP + p] = i;
}

// ---------------------------------------------------------------------------
// Reduce: one CTA per class, 256 threads, pinned to 8 CTAs/SM (<=32 regs).
// Thread t owns cols [4t, 4t+3].
// ---------------------------------------------------------------------------
__global__ __launch_bounds__(256, 8) void k_reduce_v4(
    const float* __restrict__ preds,
    const float* __restrict__ val_preds,
    float* __restrict__ out,
    int C)
{
    int c   = blockIdx.x;
    int tid = threadIdx.x;

    __shared__ int s_base[KSUB + 1];
    __shared__ int s_idx[SMAX];

    // Per-sub counts -> prefix (KSUB=8, done by thread 0; trivial).
    if (tid == 0) {
        int tot = 0;
        #pragma unroll
        for (int s = 0; s < KSUB; ++s) {
            s_base[s] = tot;
            int cs = g_cursor[c * KSUB + s];
            tot += (cs < CAP ? cs : CAP);
        }
        s_base[KSUB] = tot;
    }
    __syncthreads();

    // Cooperative stage of all row indices into smem (compacted).
    #pragma unroll
    for (int s = 0; s < KSUB; ++s) {
        int lo = s_base[s], cs = s_base[s + 1] - lo;
        const int* src = &g_rowidx[(c * KSUB + s) * CAP];
        for (int j = tid; j < cs; j += 256) s_idx[lo + j] = src[j];
    }
    __syncthreads();

    // Sole reader of this class's cursors -> reset for next graph replay.
    if (tid < KSUB) g_cursor[c * KSUB + tid] = 0;

    int cnt  = s_base[KSUB];
    int col4 = tid * 4;
    if (col4 >= C) return;

    float ax = 0.f, ay = 0.f, az = 0.f, aw = 0.f;
    int r = 0;
    // 4 independent 16B streaming loads in flight per thread
    // (the 32-register MLP maximum that preserves 8 CTAs/SM).
    for (; r + 3 < cnt; r += 4) {
        const float4* p0 = (const float4*)(preds + (size_t)s_idx[r + 0] * C + col4);
        const float4* p1 = (const float4*)(preds + (size_t)s_idx[r + 1] * C + col4);
        const float4* p2 = (const float4*)(preds + (size_t)s_idx[r + 2] * C + col4);
        const float4* p3 = (const float4*)(preds + (size_t)s_idx[r + 3] * C + col4);
        float4 v0 = __ldcs(p0);
        float4 v1 = __ldcs(p1);
        float4 v2 = __ldcs(p2);
        float4 v3 = __ldcs(p3);
        ax += v0.x; ay += v0.y; az += v0.z; aw += v0.w;
        ax += v1.x; ay += v1.y; az += v1.z; aw += v1.w;
        ax += v2.x; ay += v2.y; az += v2.z; aw += v2.w;
        ax += v3.x; ay += v3.y; az += v3.z; aw += v3.w;
    }
    for (; r < cnt; ++r) {
        float4 v = __ldcs((const float4*)(preds + (size_t)s_idx[r] * C + col4));
        ax += v.x; ay += v.y; az += v.z; aw += v.w;
    }

    float4 vp = *(const float4*)(val_preds + (size_t)c * C + col4);
    float4 o;
    if (cnt > 0) {
        float inv = ONE_MINUS_GAMMA / (float)cnt;
        o.x = ax * inv + GAMMA * vp.x;
        o.y = ay * inv + GAMMA * vp.y;
        o.z = az * inv + GAMMA * vp.z;
        o.w = aw * inv + GAMMA * vp.w;
    } else {
        o = vp;
    }
    *(float4*)(out + (size_t)c * C + col4) = o;
}

// Scalar-column fallback (C % 4 != 0 or C > 1024): 1 CTA per class.
__global__ __launch_bounds__(256) void k_reduce_s(
    const float* __restrict__ preds,
    const float* __restrict__ val_preds,
    float* __restrict__ out,
    int C)
{
    int c   = blockIdx.x;
    int tid = threadIdx.x;

    __shared__ int s_base[KSUB + 1];
    __shared__ int s_idx[SMAX];

    if (tid == 0) {
        int tot = 0;
        #pragma unroll
        for (int s = 0; s < KSUB; ++s) {
            s_base[s] = tot;
            int cs = g_cursor[c * KSUB + s];
            tot += (cs < CAP ? cs : CAP);
        }
        s_base[KSUB] = tot;
    }
    __syncthreads();
    #pragma unroll
    for (int s = 0; s < KSUB; ++s) {
        int lo = s_base[s], cs = s_base[s + 1] - lo;
        const int* src = &g_rowidx[(c * KSUB + s) * CAP];
        for (int j = tid; j < cs; j += 256) s_idx[lo + j] = src[j];
    }
    __syncthreads();
    if (tid < KSUB) g_cursor[c * KSUB + tid] = 0;

    int cnt = s_base[KSUB];
    for (int col = tid; col < C; col += 256) {
        float acc = 0.f;
        for (int r = 0; r < cnt; ++r)
            acc += __ldcs(preds + (size_t)s_idx[r] * C + col);
        float vp = val_preds[(size_t)c * C + col];
        out[(size_t)c * C + col] =
            (cnt > 0) ? (ONE_MINUS_GAMMA * acc / (float)cnt + GAMMA * vp) : vp;
    }
}

extern "C" void kernel_launch(void* const* d_in, const int* in_sizes, int n_in,
                              void* d_out, int out_size) {
    const float* preds     = (const float*)d_in[0];
    const int*   labels    = (const int*)  d_in[1];
    const float* val_preds = (const float*)d_in[2];
    float*       out       = (float*)d_out;

    const int N = in_sizes[1];       // 131072
    const int C = in_sizes[0] / N;   // 1000

    if ((N & 3) == 0) {
        int n4 = N / 4;
        k_scatter_v4<<<(n4 + 255) / 256, 256>>>((const int4*)labels, n4);
    } else {
        k_scatter_s<<<(N + 255) / 256, 256>>>(labels, N);
    }

    if ((C % 4) == 0 && C <= C_MAX) {
        k_reduce_v4<<<C, 256>>>(preds, val_preds, out, C);
    } else {
        k_reduce_s<<<C, 256>>>(preds, val_preds, out, C);
    }
}

// round 17
// speedup vs baseline: 1.0290x; 1.0248x over previous
#include <cuda_runtime.h>
#include <cuda_bf16.h>

// ValScores: per-class mean of preds rows (segment reduction by label) + EMA.
//   out[c,:] = cnt[c]>0 ? 0.1*mean_c(preds) + 0.9*val_preds[c,:] : val_preds[c,:]
//
// Structure = converged optimum (R13, 92.9us best; identical binary spans
// 92.9-95.4 run-to-run). ONE change this round: sub-buckets keyed on index
// HIGH bits (i >> shift, range-partition) instead of low bits. The reduce's
// concatenated index list becomes globally ascending -> all 1000 CTAs sweep
// preds front-to-back roughly in phase -> chip-wide outstanding gathers
// concentrate in a moving window instead of spraying the full 524MB ->
// better DRAM bank/page scheduling. Hot loop, registers, contention profile
// (~16 arrivals/cursor) all unchanged.
//
// Invariants (12 failed alternatives): whole contiguous 4000B rows per CTA;
// 32 regs / __launch_bounds__(256,8) / grid=1000 single wave; 4x float4
// __ldcs unroll; two kernels; zero cross-CTA coordination in the reduce.

#define C_MAX   1024
#define KSUB    8
#define CAP     256            // per sub-list capacity (expected ~16 +- 4)
#define SMAX    (KSUB * CAP)   // 2048 indices, 8KB smem
#define GAMMA   0.9f
#define ONE_MINUS_GAMMA 0.1f

__device__ int g_cursor[C_MAX * KSUB];        // zero-init at module load
__device__ int g_rowidx[C_MAX * KSUB * CAP];  // 8 MB scratch

// ---------------------------------------------------------------------------
// Scatter: int4 label loads (4 independent atomics/thread — best measured
// scatter form). Sub-bucket = index >> shift (range partition) so that the
// reduce's concatenated list is globally ascending.
// ---------------------------------------------------------------------------
__global__ __launch_bounds__(256) void k_scatter_v4(const int4* __restrict__ labels4,
                                                    int n4, int shift) {
    int t = blockIdx.x * blockDim.x + threadIdx.x;
    if (t >= n4) return;
    int4 L = labels4[t];
    int i0 = t * 4;

    // All 4 elements share the same range bucket except at range boundaries;
    // compute per-element for correctness.
    int s0 = (i0 + 0) >> shift; if (s0 > KSUB - 1) s0 = KSUB - 1;
    int s1 = (i0 + 1) >> shift; if (s1 > KSUB - 1) s1 = KSUB - 1;
    int s2 = (i0 + 2) >> shift; if (s2 > KSUB - 1) s2 = KSUB - 1;
    int s3 = (i0 + 3) >> shift; if (s3 > KSUB - 1) s3 = KSUB - 1;

    int b0 = L.x * KSUB + s0;
    int b1 = L.y * KSUB + s1;
    int b2 = L.z * KSUB + s2;
    int b3 = L.w * KSUB + s3;

    int p0 = atomicAdd(&g_cursor[b0], 1);
    int p1 = atomicAdd(&g_cursor[b1], 1);
    int p2 = atomicAdd(&g_cursor[b2], 1);
    int p3 = atomicAdd(&g_cursor[b3], 1);

    if (p0 < CAP) g_rowidx[b0 * CAP + p0] = i0 + 0;
    if (p1 < CAP) g_rowidx[b1 * CAP + p1] = i0 + 1;
    if (p2 < CAP) g_rowidx[b2 * CAP + p2] = i0 + 2;
    if (p3 < CAP) g_rowidx[b3 * CAP + p3] = i0 + 3;
}

// Scalar fallback for N % 4 != 0.
__global__ __launch_bounds__(256) void k_scatter_s(const int* __restrict__ labels,
                                                   int N, int shift) {
    int i = blockIdx.x * blockDim.x + threadIdx.x;
    if (i >= N) return;
    int s = i >> shift; if (s > KSUB - 1) s = KSUB - 1;
    int b = labels[i] * KSUB + s;
    int p = atomicAdd(&g_cursor[b], 1);
    if (p < CAP) g_rowidx[b * CAP + p] = i;
}

// ---------------------------------------------------------------------------
// Reduce: one CTA per class, 256 threads, pinned to 8 CTAs/SM (<=32 regs).
// Thread t owns cols [4t, 4t+3]. Hot path identical to the 92.9us winner.
// Bucket concatenation s=0..KSUB-1 now yields a range-sorted index list.
// ---------------------------------------------------------------------------
__global__ __launch_bounds__(256, 8) void k_reduce_v4(
    const float* __restrict__ preds,
    const float* __restrict__ val_preds,
    float* __restrict__ out,
    int C)
{
    int c   = blockIdx.x;
    int tid = threadIdx.x;

    __shared__ int s_base[KSUB + 1];
    __shared__ int s_idx[SMAX];

    // Per-sub counts -> prefix (KSUB=8, done by thread 0; trivial).
    if (tid == 0) {
        int tot = 0;
        #pragma unroll
        for (int s = 0; s < KSUB; ++s) {
            s_base[s] = tot;
            int cs = g_cursor[c * KSUB + s];
            tot += (cs < CAP ? cs : CAP);
        }
        s_base[KSUB] = tot;
    }
    __syncthreads();

    // Cooperative stage of all row indices into smem (compacted; ascending
    // by 16K-row range -> all CTAs sweep memory roughly in phase).
    #pragma unroll
    for (int s = 0; s < KSUB; ++s) {
        int lo = s_base[s], cs = s_base[s + 1] - lo;
        const int* src = &g_rowidx[(c * KSUB + s) * CAP];
        for (int j = tid; j < cs; j += 256) s_idx[lo + j] = src[j];
    }
    __syncthreads();

    // Sole reader of this class's cursors -> reset for next graph replay.
    if (tid < KSUB) g_cursor[c * KSUB + tid] = 0;

    int cnt  = s_base[KSUB];
    int col4 = tid * 4;
    if (col4 >= C) return;

    float ax = 0.f, ay = 0.f, az = 0.f, aw = 0.f;
    int r = 0;
    // 4 independent 16B streaming loads in flight per thread
    // (the 32-register MLP maximum that preserves 8 CTAs/SM).
    for (; r + 3 < cnt; r += 4) {
        const float4* p0 = (const float4*)(preds + (size_t)s_idx[r + 0] * C + col4);
        const float4* p1 = (const float4*)(preds + (size_t)s_idx[r + 1] * C + col4);
        const float4* p2 = (const float4*)(preds + (size_t)s_idx[r + 2] * C + col4);
        const float4* p3 = (const float4*)(preds + (size_t)s_idx[r + 3] * C + col4);
        float4 v0 = __ldcs(p0);
        float4 v1 = __ldcs(p1);
        float4 v2 = __ldcs(p2);
        float4 v3 = __ldcs(p3);
        ax += v0.x; ay += v0.y; az += v0.z; aw += v0.w;
        ax += v1.x; ay += v1.y; az += v1.z; aw += v1.w;
        ax += v2.x; ay += v2.y; az += v2.z; aw += v2.w;
        ax += v3.x; ay += v3.y; az += v3.z; aw += v3.w;
    }
    for (; r < cnt; ++r) {
        float4 v = __ldcs((const float4*)(preds + (size_t)s_idx[r] * C + col4));
        ax += v.x; ay += v.y; az += v.z; aw += v.w;
    }

    float4 vp = *(const float4*)(val_preds + (size_t)c * C + col4);
    float4 o;
    if (cnt > 0) {
        float inv = ONE_MINUS_GAMMA / (float)cnt;
        o.x = ax * inv + GAMMA * vp.x;
        o.y = ay * inv + GAMMA * vp.y;
        o.z = az * inv + GAMMA * vp.z;
        o.w = aw * inv + GAMMA * vp.w;
    } else {
        o = vp;
    }
    *(float4*)(out + (size_t)c * C + col4) = o;
}

// Scalar-column fallback (C % 4 != 0 or C > 1024): 1 CTA per class.
__global__ __launch_bounds__(256) void k_reduce_s(
    const float* __restrict__ preds,
    const float* __restrict__ val_preds,
    float* __restrict__ out,
    int C)
{
    int c   = blockIdx.x;
    int tid = threadIdx.x;

    __shared__ int s_base[KSUB + 1];
    __shared__ int s_idx[SMAX];

    if (tid == 0) {
        int tot = 0;
        #pragma unroll
        for (int s = 0; s < KSUB; ++s) {
            s_base[s] = tot;
            int cs = g_cursor[c * KSUB + s];
            tot += (cs < CAP ? cs : CAP);
        }
        s_base[KSUB] = tot;
    }
    __syncthreads();
    #pragma unroll
    for (int s = 0; s < KSUB; ++s) {
        int lo = s_base[s], cs = s_base[s + 1] - lo;
        const int* src = &g_rowidx[(c * KSUB + s) * CAP];
        for (int j = tid; j < cs; j += 256) s_idx[lo + j] = src[j];
    }
    __syncthreads();
    if (tid < KSUB) g_cursor[c * KSUB + tid] = 0;

    int cnt = s_base[KSUB];
    for (int col = tid; col < C; col += 256) {
        float acc = 0.f;
        for (int r = 0; r < cnt; ++r)
            acc += __ldcs(preds + (size_t)s_idx[r] * C + col);
        float vp = val_preds[(size_t)c * C + col];
        out[(size_t)c * C + col] =
            (cnt > 0) ? (ONE_MINUS_GAMMA * acc / (float)cnt + GAMMA * vp) : vp;
    }
}

extern "C" void kernel_launch(void* const* d_in, const int* in_sizes, int n_in,
                              void* d_out, int out_size) {
    const float* preds     = (const float*)d_in[0];
    const int*   labels    = (const int*)  d_in[1];
    const float* val_preds = (const float*)d_in[2];
    float*       out       = (float*)d_out;

    const int N = in_sizes[1];       // 131072
    const int C = in_sizes[0] / N;   // 1000

    // shift s.t. (1<<shift)*KSUB >= N  -> KSUB equal index ranges.
    int shift = 0;
    while ((1 << shift) * KSUB < N) ++shift;

    if ((N & 3) == 0) {
        int n4 = N / 4;
        k_scatter_v4<<<(n4 + 255) / 256, 256>>>((const int4*)labels, n4, shift);
    } else {
        k_scatter_s<<<(N + 255) / 256, 256>>>(labels, N, shift);
    }

    if ((C % 4) == 0 && C <= C_MAX) {
        k_reduce_v4<<<C, 256>>>(preds, val_preds, out, C);
    } else {
        k_reduce_s<<<C, 256>>>(preds, val_preds, out, C);
    }
}